// round 4
// baseline (speedup 1.0000x reference)
#include <cuda_runtime.h>
#include <cstdint>

typedef unsigned long long u64;
#define DEVINL __device__ __forceinline__

DEVINL u64 pack2(float lo, float hi) {
    u64 d;
    asm("mov.b64 %0, {%1, %2};" : "=l"(d) : "f"(lo), "f"(hi));
    return d;
}
DEVINL void unpack2(u64 v, float& lo, float& hi) {
    asm("mov.b64 {%0, %1}, %2;" : "=f"(lo), "=f"(hi) : "l"(v));
}
DEVINL u64 ffma2(u64 a, u64 b, u64 c) {
    u64 d;
    asm("fma.rn.f32x2 %0, %1, %2, %3;" : "=l"(d) : "l"(a), "l"(b), "l"(c));
    return d;
}

// smooth_leaky_relu(x) = 0.6x + 0.4x*tanh(x/2)   (alpha=0.2)
DEVINL float act_fn(float v) {
    float t;
    asm("tanh.approx.f32 %0, %1;" : "=f"(t) : "f"(0.5f * v));
    return v * (0.6f + 0.4f * t);
}

static constexpr int ROWLEN = 592;

// g_wt layout (floats):
//  [0, 16384)      seg0 Wt natural [k][o]           128x128
//  [16384, 24576)  seg1 Wt duplicated [k][o][2]     64x64x2
//  [24576, 26624)  seg2 Wt duplicated [k][o][2]     32x32x2
//  [26624, 27136)  seg3 Wt duplicated [k][o][2]     16x16x2
__device__ float g_wt[27136];

__global__ void prep_kernel(const float* __restrict__ w0, const float* __restrict__ w1,
                            const float* __restrict__ w2, const float* __restrict__ w3) {
    int idx = blockIdx.x * 256 + threadIdx.x;
    if (idx < 16384) {
        int k = idx >> 7, o = idx & 127;
        g_wt[idx] = w0[o * 128 + k];
    } else if (idx < 24576) {
        int t = idx - 16384; int k = t >> 7, o = (t & 127) >> 1;
        g_wt[idx] = w1[o * 64 + k];
    } else if (idx < 26624) {
        int t = idx - 24576; int k = t >> 6, o = (t & 63) >> 1;
        g_wt[idx] = w2[o * 32 + k];
    } else if (idx < 27136) {
        int t = idx - 26624; int k = t >> 5, o = (t & 31) >> 1;
        g_wt[idx] = w3[o * 16 + k];
    }
}

// ============ seg0: MUL=128, D=1, scheme-0 (X duplicated, W natural pairs) ============
// R=64 rows, 8 warps, each warp = 16 outputs (TOH=8 w-pairs), TC=2 columns/thread.
// KPH=2 phases over k (X half-buffer 32KB, aliases Os after GEMM).
__global__ __launch_bounds__(256, 2)
void seg0_kernel(const float* __restrict__ x, const float* __restrict__ bias,
                 float* __restrict__ out, int N) {
    constexpr int R = 64, MUL = 128, KCH = 64;
    constexpr int PXu = R + 1;        // u64 pitch (65)
    constexpr int PO  = MUL + 1;      // 129

    extern __shared__ float smem[];
    float* Ws = smem;                         // 16384 floats [k][o]
    u64*   Xd = (u64*)(smem + 16384);         // KCH x PXu u64 (8320 floats)
    float* Os = smem + 16384;                 // aliases Xd after GEMM

    const int tid = threadIdx.x, lane = tid & 31, warp = tid >> 5;
    const int r0 = blockIdx.x * R;
    const int nrows = min(R, N - r0);
    const int ob = warp * 16;

    #pragma unroll 1
    for (int i = tid; i < 16384 / 4; i += 256)
        ((float4*)Ws)[i] = ((const float4*)g_wt)[i];

    u64 acc[2][8];
    #pragma unroll
    for (int p = 0; p < 8; p++) {
        u64 bp = pack2(__ldg(bias + ob + 2 * p), __ldg(bias + ob + 2 * p + 1));
        acc[0][p] = bp; acc[1][p] = bp;
    }

    const int nld = nrows * 16;   // 64 floats/row per phase = 16 float4
    #pragma unroll
    for (int ph = 0; ph < 2; ph++) {
        if (ph) __syncthreads();
        #pragma unroll 1
        for (int i = tid; i < nld; i += 256) {
            int r = i >> 4, q = i & 15;
            float4 v = *(const float4*)(x + (size_t)(r0 + r) * ROWLEN + ph * 64 + 4 * q);
            Xd[(4 * q + 0) * PXu + r] = pack2(v.x, v.x);
            Xd[(4 * q + 1) * PXu + r] = pack2(v.y, v.y);
            Xd[(4 * q + 2) * PXu + r] = pack2(v.z, v.z);
            Xd[(4 * q + 3) * PXu + r] = pack2(v.w, v.w);
        }
        __syncthreads();

        #pragma unroll 4
        for (int kl = 0; kl < KCH; kl++) {
            u64 x0 = Xd[kl * PXu + lane];
            u64 x1 = Xd[kl * PXu + lane + 32];
            const u64* wrow = (const u64*)(Ws + (ph * KCH + kl) * MUL + ob);
            #pragma unroll
            for (int p = 0; p < 8; p++) {
                u64 wp = wrow[p];
                acc[0][p] = ffma2(x0, wp, acc[0][p]);
                acc[1][p] = ffma2(x1, wp, acc[1][p]);
            }
        }
    }
    __syncthreads();

    #pragma unroll
    for (int i = 0; i < 2; i++) {
        int c = lane + 32 * i;
        #pragma unroll
        for (int p = 0; p < 8; p++) {
            float lo, hi; unpack2(acc[i][p], lo, hi);
            Os[c * PO + ob + 2 * p]     = lo;
            Os[c * PO + ob + 2 * p + 1] = hi;
        }
    }
    __syncthreads();

    const int nst = nrows * 32;   // 128 outputs/row = 32 float4
    #pragma unroll 1
    for (int i = tid; i < nst; i += 256) {
        int r = i >> 5, q = i & 31;
        float4 v;
        v.x = act_fn(Os[r * PO + 4 * q + 0]);
        v.y = act_fn(Os[r * PO + 4 * q + 1]);
        v.z = act_fn(Os[r * PO + 4 * q + 2]);
        v.w = act_fn(Os[r * PO + 4 * q + 3]);
        *(float4*)(out + (size_t)(r0 + r) * ROWLEN + 4 * q) = v;
    }
}

// ============ scheme-1 template (seg1/2/3): X natural pairs, W pre-duplicated ============
// Thread tile: TC columns (TC/2 u64 pairs) x TO outputs.  Warps = OW output-groups x CW column-groups.
template<int MUL, int D, int DPAD, int R, int NW, int CW, int TO,
         int IN_OFF, int WOFF, int MINB>
__global__ __launch_bounds__(NW * 32, MINB)
void seg_s1_kernel(const float* __restrict__ x, const float* __restrict__ bias,
                   float* __restrict__ out, int N) {
    constexpr int NT     = NW * 32;
    constexpr int K      = MUL;
    constexpr int CBLK   = R * DPAD;
    constexpr int OW     = NW / CW;
    constexpr int CPW    = CBLK / CW;
    constexpr int TC     = CPW / 32;
    constexpr int PAIRS  = TC / 2;
    constexpr int PX     = CBLK + 2;
    constexpr int PO     = MUL + 1;
    constexpr int SEGLEN = MUL * D;
    constexpr int SEGF4  = SEGLEN / 4;
    constexpr int WD_F   = K * MUL * 2;
    static_assert(OW * TO == MUL, "");
    static_assert(TC % 2 == 0, "");

    extern __shared__ float smem[];
    float* Wd = smem;            // duplicated weights [k][o][2]
    float* Xs = smem + WD_F;     // [k][col], pitch PX
    float* Os = Xs;              // alias after GEMM

    const int tid = threadIdx.x, lane = tid & 31, warp = tid >> 5;
    const int r0 = blockIdx.x * R;
    const int nrows = min(R, N - r0);
    const int ow = warp % OW, cg = warp / OW;
    const int ob = ow * TO;
    const int cbase = cg * CPW + 2 * lane;

    #pragma unroll 1
    for (int i = tid; i < WD_F / 4; i += NT)
        ((float4*)Wd)[i] = ((const float4*)(g_wt + WOFF))[i];

    // ---- X load + transpose scatter (pad columns zeroed by the dd==D-1 owner) ----
    const int nld = nrows * SEGF4;
    #pragma unroll 1
    for (int i = tid; i < nld; i += NT) {
        int r = i / SEGF4, q = i - r * SEGF4;
        float4 v = *(const float4*)(x + (size_t)(r0 + r) * ROWLEN + IN_OFF + 4 * q);
        float vv[4] = {v.x, v.y, v.z, v.w};
        int j = 4 * q;
        #pragma unroll
        for (int e = 0; e < 4; e++) {
            int jj = j + e;
            int k  = jj / D;
            int dd = jj - k * D;
            Xs[k * PX + r * DPAD + dd] = vv[e];
            if (DPAD > D && dd == D - 1) {
                #pragma unroll
                for (int z = D; z < DPAD; z++)
                    Xs[k * PX + r * DPAD + z] = 0.0f;
            }
        }
    }
    __syncthreads();

    u64 acc[PAIRS][TO];
    #pragma unroll
    for (int t = 0; t < TO; t++) {
        float b = __ldg(bias + ob + t);
        u64 bp = pack2(b, b);
        #pragma unroll
        for (int i = 0; i < PAIRS; i++) acc[i][t] = bp;
    }

    #pragma unroll 4
    for (int k = 0; k < K; k++) {
        u64 xp[PAIRS];
        #pragma unroll
        for (int i = 0; i < PAIRS; i++)
            xp[i] = *(const u64*)(Xs + k * PX + cbase + 64 * i);
        const u64* wrow = (const u64*)Wd + k * MUL + ob;
        #pragma unroll
        for (int t = 0; t < TO; t++) {
            u64 wp = wrow[t];
            #pragma unroll
            for (int i = 0; i < PAIRS; i++)
                acc[i][t] = ffma2(xp[i], wp, acc[i][t]);
        }
    }
    __syncthreads();

    // ---- stage accumulators ----
    #pragma unroll
    for (int i = 0; i < PAIRS; i++) {
        int c = cg * CPW + 2 * lane + 64 * i;
        #pragma unroll
        for (int t = 0; t < TO; t++) {
            float lo, hi; unpack2(acc[i][t], lo, hi);
            Os[c * PO + ob + t]       = lo;
            Os[(c + 1) * PO + ob + t] = hi;
        }
    }
    __syncthreads();

    // ---- epilogue: coalesced float4 store ----
    #pragma unroll 1
    for (int i = tid; i < nld; i += NT) {
        int r = i / SEGF4, q = i - r * SEGF4;
        int j = 4 * q;
        float vv[4];
        #pragma unroll
        for (int e = 0; e < 4; e++) {
            int jj = j + e;
            int o  = jj / D;
            int dd = jj - o * D;
            vv[e] = Os[(r * DPAD + dd) * PO + o];
        }
        float4 v; v.x = vv[0]; v.y = vv[1]; v.z = vv[2]; v.w = vv[3];
        *(float4*)(out + (size_t)(r0 + r) * ROWLEN + IN_OFF + 4 * q) = v;
    }
}

extern "C" void kernel_launch(void* const* d_in, const int* in_sizes, int n_in,
                              void* d_out, int out_size) {
    const float* x  = (const float*)d_in[0];
    const float* w0 = (const float*)d_in[1];
    const float* w1 = (const float*)d_in[2];
    const float* w2 = (const float*)d_in[3];
    const float* w3 = (const float*)d_in[4];
    const float* b0 = (const float*)d_in[5];
    const float* b1 = (const float*)d_in[6];
    const float* b2 = (const float*)d_in[7];
    const float* b3 = (const float*)d_in[8];
    float* out = (float*)d_out;
    const int N = in_sizes[0] / ROWLEN;

    //                   MUL  D DPAD   R NW CW TO IN_OFF  WOFF  MINB
    auto k1 = seg_s1_kernel<64, 3, 3, 64, 8, 1, 8,  128, 16384, 2>;
    auto k2 = seg_s1_kernel<32, 5, 6, 64, 8, 2, 8,  320, 24576, 2>;
    auto k3 = seg_s1_kernel<16, 7, 8, 32, 4, 2, 8,  480, 26624, 6>;

    constexpr int S0 = (16384 + 64 * 65 * 2) * 4;          // 98816: Ws + max(Xd, Os)
    constexpr int S1 = (64 * 64 * 2 + 192 * 65) * 4;       // 82688
    constexpr int S2 = (32 * 32 * 2 + 384 * 33) * 4;       // 58880
    constexpr int S3 = (16 * 16 * 2 + 256 * 17) * 4;       // 19456

    cudaFuncSetAttribute(seg0_kernel, cudaFuncAttributeMaxDynamicSharedMemorySize, S0);
    cudaFuncSetAttribute(k1, cudaFuncAttributeMaxDynamicSharedMemorySize, S1);
    cudaFuncSetAttribute(k2, cudaFuncAttributeMaxDynamicSharedMemorySize, S2);
    cudaFuncSetAttribute(k3, cudaFuncAttributeMaxDynamicSharedMemorySize, S3);

    prep_kernel<<<106, 256>>>(w0, w1, w2, w3);

    const int g64 = (N + 63) / 64;   // 1563
    const int g32 = (N + 31) / 32;   // 3125
    seg0_kernel<<<g64, 256, S0>>>(x, b0, out, N);
    k1<<<g64, 256, S1>>>(x, b1, out, N);
    k2<<<g64, 256, S2>>>(x, b2, out, N);
    k3<<<g32, 128, S3>>>(x, b3, out, N);
}

// round 5
// speedup vs baseline: 1.0817x; 1.0817x over previous
#include <cuda_runtime.h>
#include <cstdint>

typedef unsigned long long u64;
#define DEVINL __device__ __forceinline__

DEVINL u64 pack2(float lo, float hi) {
    u64 d;
    asm("mov.b64 %0, {%1, %2};" : "=l"(d) : "f"(lo), "f"(hi));
    return d;
}
DEVINL void unpack2(u64 v, float& lo, float& hi) {
    asm("mov.b64 {%0, %1}, %2;" : "=f"(lo), "=f"(hi) : "l"(v));
}
DEVINL u64 ffma2(u64 a, u64 b, u64 c) {
    u64 d;
    asm("fma.rn.f32x2 %0, %1, %2, %3;" : "=l"(d) : "l"(a), "l"(b), "l"(c));
    return d;
}

// smooth_leaky_relu(x) = 0.6x + 0.4x*tanh(x/2)   (alpha=0.2)
DEVINL float act_fn(float v) {
    float t;
    asm("tanh.approx.f32 %0, %1;" : "=f"(t) : "f"(0.5f * v));
    return v * (0.6f + 0.4f * t);
}

static constexpr int ROWLEN = 592;

// g_wt layout (floats):
//  [0, 16384)      seg0 Wt natural [k][o]        128x128
//  [16384, 20480)  seg1 Wt natural [k][o]        64x64
//  [20480, 22528)  seg2 Wt duplicated [k][o][2]  32x32x2
//  [22528, 22784)  seg3 Wt natural [k][o]        16x16
__device__ float g_wt[22784];

__global__ void prep_kernel(const float* __restrict__ w0, const float* __restrict__ w1,
                            const float* __restrict__ w2, const float* __restrict__ w3) {
    int idx = blockIdx.x * 256 + threadIdx.x;
    if (idx < 16384) {
        int k = idx >> 7, o = idx & 127;
        g_wt[idx] = w0[o * 128 + k];
    } else if (idx < 20480) {
        int t = idx - 16384; int k = t >> 6, o = t & 63;
        g_wt[idx] = w1[o * 64 + k];
    } else if (idx < 22528) {
        int t = idx - 20480; int k = t >> 6, o = (t & 63) >> 1;
        g_wt[idx] = w2[o * 32 + k];
    } else if (idx < 22784) {
        int t = idx - 22528; int k = t >> 4, o = t & 15;
        g_wt[idx] = w3[o * 16 + k];
    }
}

// ===================== scheme-0 template (seg0/1/3) =====================
// Xd: duplicated u64 pairs {x,x}, layout [k][col], pitch PXu=CBLK+1 (u64).
// Ws: natural [k][o]; each warp reads o-pairs as broadcast LDS.64.
// Warps = OW o-groups (TO outputs each) x CW column groups.
// K loaded in KPH phases reusing one buffer; Os aliases Xd after GEMM.
template<int MUL, int D, int DPAD, int R, int NW, int CW, int TO, int KPH,
         int IN_OFF, int WOFF, bool ACT, int MINB>
__global__ __launch_bounds__(NW * 32, MINB)
void seg_s0(const float* __restrict__ x, const float* __restrict__ bias,
            float* __restrict__ out, int N) {
    constexpr int NT     = NW * 32;
    constexpr int CBLK   = R * DPAD;
    constexpr int OW     = NW / CW;
    constexpr int CPW    = CBLK / CW;
    constexpr int TC     = CPW / 32;
    constexpr int TOH    = TO / 2;
    constexpr int SEGLEN = MUL * D;
    constexpr int SEGF4  = SEGLEN / 4;
    constexpr int KCH    = MUL / KPH;
    constexpr int CHLEN  = SEGLEN / KPH;
    constexpr int CHF4   = CHLEN / 4;
    constexpr int PXu    = CBLK + 1;
    constexpr int PO     = MUL + 1;
    static_assert(OW * TO == MUL, "");
    static_assert(CPW % 32 == 0, "");

    extern __shared__ float smem[];
    float* Ws = smem;                        // MUL*MUL
    u64*   Xd = (u64*)(smem + MUL * MUL);    // KCH x PXu u64
    float* Os = smem + MUL * MUL;            // alias after GEMM

    const int tid = threadIdx.x, lane = tid & 31, warp = tid >> 5;
    const int r0 = blockIdx.x * R;
    const int nrows = min(R, N - r0);
    const int ob = (warp % OW) * TO;
    const int cbase = (warp / OW) * CPW + lane;

    #pragma unroll 1
    for (int i = tid; i < MUL * MUL / 4; i += NT)
        ((float4*)Ws)[i] = ((const float4*)(g_wt + WOFF))[i];

    u64 acc[TC][TOH];
    #pragma unroll
    for (int p = 0; p < TOH; p++) {
        u64 bp = pack2(__ldg(bias + ob + 2 * p), __ldg(bias + ob + 2 * p + 1));
        #pragma unroll
        for (int i = 0; i < TC; i++) acc[i][p] = bp;
    }

    const int nld = nrows * CHF4;
    #pragma unroll
    for (int ph = 0; ph < KPH; ph++) {
        if (ph) __syncthreads();
        #pragma unroll 1
        for (int i = tid; i < nld; i += NT) {
            int r = i / CHF4, q = i - r * CHF4;
            float4 v = *(const float4*)(x + (size_t)(r0 + r) * ROWLEN + IN_OFF + ph * CHLEN + 4 * q);
            float vv[4] = {v.x, v.y, v.z, v.w};
            int j = 4 * q;
            #pragma unroll
            for (int e = 0; e < 4; e++) {
                int jj = j + e;
                int kl = jj / D;
                int dd = jj - kl * D;
                Xd[kl * PXu + r * DPAD + dd] = pack2(vv[e], vv[e]);
                if (DPAD > D && dd == D - 1) {
                    #pragma unroll
                    for (int z = D; z < DPAD; z++)
                        Xd[kl * PXu + r * DPAD + z] = pack2(0.0f, 0.0f);
                }
            }
        }
        __syncthreads();

        #pragma unroll 4
        for (int kl = 0; kl < KCH; kl++) {
            u64 xd[TC];
            #pragma unroll
            for (int i = 0; i < TC; i++)
                xd[i] = Xd[kl * PXu + cbase + 32 * i];
            const u64* wrow = (const u64*)(Ws + (ph * KCH + kl) * MUL + ob);
            #pragma unroll
            for (int p = 0; p < TOH; p++) {
                u64 wp = wrow[p];
                #pragma unroll
                for (int i = 0; i < TC; i++)
                    acc[i][p] = ffma2(xd[i], wp, acc[i][p]);
            }
        }
    }
    __syncthreads();

    // ---- stage accumulators: Os[col][o], PO odd -> conflict-free ----
    #pragma unroll
    for (int i = 0; i < TC; i++) {
        int c = cbase + 32 * i;
        #pragma unroll
        for (int p = 0; p < TOH; p++) {
            float lo, hi; unpack2(acc[i][p], lo, hi);
            Os[c * PO + ob + 2 * p]     = lo;
            Os[c * PO + ob + 2 * p + 1] = hi;
        }
    }
    __syncthreads();

    // ---- epilogue: coalesced float4 store ----
    const int nst = nrows * SEGF4;
    #pragma unroll 1
    for (int i = tid; i < nst; i += NT) {
        int r = i / SEGF4, q = i - r * SEGF4;
        int j = 4 * q;
        float vv[4];
        #pragma unroll
        for (int e = 0; e < 4; e++) {
            int jj = j + e;
            int o  = jj / D;
            int dd = jj - o * D;
            float v = Os[(r * DPAD + dd) * PO + o];
            if (ACT) v = act_fn(v);
            vv[e] = v;
        }
        float4 v; v.x = vv[0]; v.y = vv[1]; v.z = vv[2]; v.w = vv[3];
        *(float4*)(out + (size_t)(r0 + r) * ROWLEN + IN_OFF + 4 * q) = v;
    }
}

// ===================== seg2: scheme-1, unpadded D=5, W pre-duplicated =====================
// 8 warps x (TO=4 outputs, TC=10 cols as 5 u64 pairs). R=64 rows, CBLK=320.
__global__ __launch_bounds__(256, 4)
void seg2_kernel(const float* __restrict__ x, const float* __restrict__ bias,
                 float* __restrict__ out, int N) {
    constexpr int MUL = 32, D = 5, R = 64;
    constexpr int CBLK = R * D;            // 320
    constexpr int TO = 4, PAIRS = 5;
    constexpr int SEGF4 = MUL * D / 4;     // 40
    constexpr int PX = CBLK + 2;           // 322
    constexpr int PO = MUL + 1;            // 33
    constexpr int WD_F = MUL * MUL * 2;    // 2048

    extern __shared__ float smem[];
    float* Wd = smem;                  // duplicated [k][o][2]
    float* Xs = smem + WD_F;           // [k][col] pitch PX
    float* Os = Xs;                    // alias

    const int tid = threadIdx.x, lane = tid & 31, warp = tid >> 5;
    const int r0 = blockIdx.x * R;
    const int nrows = min(R, N - r0);
    const int ob = warp * TO;
    const int cbase = 2 * lane;

    #pragma unroll 1
    for (int i = tid; i < WD_F / 4; i += 256)
        ((float4*)Wd)[i] = ((const float4*)(g_wt + 20480))[i];

    const int nld = nrows * SEGF4;
    #pragma unroll 1
    for (int i = tid; i < nld; i += 256) {
        int r = i / SEGF4, q = i - r * SEGF4;
        float4 v = *(const float4*)(x + (size_t)(r0 + r) * ROWLEN + 320 + 4 * q);
        float vv[4] = {v.x, v.y, v.z, v.w};
        int j = 4 * q;
        #pragma unroll
        for (int e = 0; e < 4; e++) {
            int jj = j + e;
            int k  = jj / D;
            int dd = jj - k * D;
            Xs[k * PX + r * D + dd] = vv[e];
        }
    }
    __syncthreads();

    u64 acc[PAIRS][TO];
    #pragma unroll
    for (int t = 0; t < TO; t++) {
        float b = __ldg(bias + ob + t);
        u64 bp = pack2(b, b);
        #pragma unroll
        for (int i = 0; i < PAIRS; i++) acc[i][t] = bp;
    }

    #pragma unroll 4
    for (int k = 0; k < MUL; k++) {
        u64 xp[PAIRS];
        #pragma unroll
        for (int i = 0; i < PAIRS; i++)
            xp[i] = *(const u64*)(Xs + k * PX + cbase + 64 * i);
        const u64* wrow = (const u64*)Wd + k * MUL + ob;
        #pragma unroll
        for (int t = 0; t < TO; t++) {
            u64 wp = wrow[t];
            #pragma unroll
            for (int i = 0; i < PAIRS; i++)
                acc[i][t] = ffma2(xp[i], wp, acc[i][t]);
        }
    }
    __syncthreads();

    #pragma unroll
    for (int i = 0; i < PAIRS; i++) {
        int c = cbase + 64 * i;
        #pragma unroll
        for (int t = 0; t < TO; t++) {
            float lo, hi; unpack2(acc[i][t], lo, hi);
            Os[c * PO + ob + t]       = lo;
            Os[(c + 1) * PO + ob + t] = hi;
        }
    }
    __syncthreads();

    #pragma unroll 1
    for (int i = tid; i < nld; i += 256) {
        int r = i / SEGF4, q = i - r * SEGF4;
        int j = 4 * q;
        float vv[4];
        #pragma unroll
        for (int e = 0; e < 4; e++) {
            int jj = j + e;
            int o  = jj / D;
            int dd = jj - o * D;
            vv[e] = Os[(r * D + dd) * PO + o];
        }
        float4 v; v.x = vv[0]; v.y = vv[1]; v.z = vv[2]; v.w = vv[3];
        *(float4*)(out + (size_t)(r0 + r) * ROWLEN + 320 + 4 * q) = v;
    }
}

extern "C" void kernel_launch(void* const* d_in, const int* in_sizes, int n_in,
                              void* d_out, int out_size) {
    const float* x  = (const float*)d_in[0];
    const float* w0 = (const float*)d_in[1];
    const float* w1 = (const float*)d_in[2];
    const float* w2 = (const float*)d_in[3];
    const float* w3 = (const float*)d_in[4];
    const float* b0 = (const float*)d_in[5];
    const float* b1 = (const float*)d_in[6];
    const float* b2 = (const float*)d_in[7];
    const float* b3 = (const float*)d_in[8];
    float* out = (float*)d_out;
    const int N = in_sizes[0] / ROWLEN;

    //              MUL  D DPAD   R  NW CW TO KPH IN_OFF  WOFF   ACT  MINB
    auto k0 = seg_s0<128, 1, 1,  64, 16, 1,  8, 2,    0,     0,  true, 2>;
    auto k1 = seg_s0< 64, 3, 3,  32,  8, 1,  8, 2,  128, 16384, false, 5>;
    auto k3 = seg_s0< 16, 7, 8,  16,  4, 2,  8, 1,  480, 22528, false, 12>;

    // smem bytes: (W + max(Xd_u64*2, Os)) * 4
    constexpr int S0 = (16384 + ((64 * 65 * 2 > 64 * 129) ? 64 * 65 * 2 : 64 * 129)) * 4;   // 98816
    constexpr int S1 = (4096  + ((32 * 97 * 2 > 96 * 65) ? 32 * 97 * 2 : 96 * 65)) * 4;     // 41344
    constexpr int S2 = (2048  + ((32 * 322 > 320 * 33) ? 32 * 322 : 320 * 33)) * 4;         // 50432
    constexpr int S3 = (256   + ((16 * 129 * 2 > 128 * 17) ? 16 * 129 * 2 : 128 * 17)) * 4; // 17536

    cudaFuncSetAttribute(k0, cudaFuncAttributeMaxDynamicSharedMemorySize, S0);
    cudaFuncSetAttribute(k1, cudaFuncAttributeMaxDynamicSharedMemorySize, S1);
    cudaFuncSetAttribute(seg2_kernel, cudaFuncAttributeMaxDynamicSharedMemorySize, S2);
    cudaFuncSetAttribute(k3, cudaFuncAttributeMaxDynamicSharedMemorySize, S3);

    prep_kernel<<<89, 256>>>(w0, w1, w2, w3);

    k0<<<(N + 63) / 64, 512, S0>>>(x, b0, out, N);
    k1<<<(N + 31) / 32, 256, S1>>>(x, b1, out, N);
    seg2_kernel<<<(N + 63) / 64, 256, S2>>>(x, b2, out, N);
    k3<<<(N + 15) / 16, 128, S3>>>(x, b3, out, N);
}

// round 6
// speedup vs baseline: 1.2278x; 1.1351x over previous
#include <cuda_runtime.h>
#include <cstdint>

typedef unsigned long long u64;
#define DEVINL __device__ __forceinline__

DEVINL u64 pack2(float lo, float hi) {
    u64 d;
    asm("mov.b64 %0, {%1, %2};" : "=l"(d) : "f"(lo), "f"(hi));
    return d;
}
DEVINL void unpack2(u64 v, float& lo, float& hi) {
    asm("mov.b64 {%0, %1}, %2;" : "=f"(lo), "=f"(hi) : "l"(v));
}
DEVINL u64 ffma2(u64 a, u64 b, u64 c) {
    u64 d;
    asm("fma.rn.f32x2 %0, %1, %2, %3;" : "=l"(d) : "l"(a), "l"(b), "l"(c));
    return d;
}

// smooth_leaky_relu(x) = 0.6x + 0.4x*tanh(x/2)   (alpha=0.2)
DEVINL float act_fn(float v) {
    float t;
    asm("tanh.approx.f32 %0, %1;" : "=f"(t) : "f"(0.5f * v));
    return v * (0.6f + 0.4f * t);
}

static constexpr int ROWLEN = 592;

// transposed weights, natural [k][o], packed back-to-back
__device__ float g_wt[21760];

__global__ void prep_kernel(const float* __restrict__ w0, const float* __restrict__ w1,
                            const float* __restrict__ w2, const float* __restrict__ w3) {
    int idx = blockIdx.x * 256 + threadIdx.x;
    if (idx < 16384) {
        int k = idx >> 7, o = idx & 127;
        g_wt[idx] = w0[o * 128 + k];
    } else if (idx < 20480) {
        int t = idx - 16384; int k = t >> 6, o = t & 63;
        g_wt[idx] = w1[o * 64 + k];
    } else if (idx < 21504) {
        int t = idx - 20480; int k = t >> 5, o = t & 31;
        g_wt[idx] = w2[o * 32 + k];
    } else if (idx < 21760) {
        int t = idx - 21504; int k = t >> 4, o = t & 15;
        g_wt[idx] = w3[o * 16 + k];
    }
}

// ===================== universal scheme-0 kernel =====================
// Xs: natural floats [k][col], pitch PX = CBLK+1 (odd -> conflict-free lane reads)
// Ws: natural [k][o]; warp reads o-pairs 4-at-a-time via LDS.128 broadcast (1 wf)
// x read as scalar LDS (1 wf per 32 cols), duplicated {x,x} in registers (ALU mov)
// Warps: OW output-groups (TO outputs) x CW column-groups (CPW columns).
// acc: TC x TO/2 u64, each u64 = two adjacent outputs for one column.
// Os aliases Xs after GEMM; staging conflict-free (odd PO pitch).
template<int MUL, int D, int R, int NW, int CW, int TO,
         int IN_OFF, int WOFF, bool ACT, int MINB>
__global__ __launch_bounds__(NW * 32, MINB)
void seg_s0(const float* __restrict__ x, const float* __restrict__ bias,
            float* __restrict__ out, int N) {
    constexpr int NT     = NW * 32;
    constexpr int K      = MUL;
    constexpr int CBLK   = R * D;
    constexpr int OW     = NW / CW;
    constexpr int CPW    = CBLK / CW;
    constexpr int TC     = CPW / 32;
    constexpr int TOH    = TO / 2;
    constexpr int TOQ    = TO / 4;
    constexpr int SEGF4  = MUL * D / 4;
    constexpr int PX     = CBLK + 1;
    constexpr int PO     = MUL + 1;
    static_assert(OW * TO == MUL, "");
    static_assert(CPW % 32 == 0, "");
    static_assert(TO % 4 == 0, "");

    extern __shared__ float smem[];
    float* Ws = smem;                   // K*MUL
    float* Xs = smem + K * MUL;         // [k][col]
    float* Os = Xs;                     // alias after GEMM

    const int tid = threadIdx.x, lane = tid & 31, warp = tid >> 5;
    const int r0 = blockIdx.x * R;
    const int nrows = min(R, N - r0);
    const int ob = (warp % OW) * TO;
    const int cbase = (warp / OW) * CPW + lane;

    #pragma unroll 1
    for (int i = tid; i < K * MUL / 4; i += NT)
        ((float4*)Ws)[i] = ((const float4*)(g_wt + WOFF))[i];

    // ---- X load + transpose scatter (natural scalars) ----
    const int nld = nrows * SEGF4;
    #pragma unroll 1
    for (int i = tid; i < nld; i += NT) {
        int r = i / SEGF4, q = i - r * SEGF4;
        float4 v = *(const float4*)(x + (size_t)(r0 + r) * ROWLEN + IN_OFF + 4 * q);
        float vv[4] = {v.x, v.y, v.z, v.w};
        int j = 4 * q;
        #pragma unroll
        for (int e = 0; e < 4; e++) {
            int jj = j + e;
            int kl = jj / D;
            int dd = jj - kl * D;
            Xs[kl * PX + r * D + dd] = vv[e];
        }
    }

    u64 acc[TC][TOH];
    #pragma unroll
    for (int p = 0; p < TOH; p++) {
        u64 bp = pack2(__ldg(bias + ob + 2 * p), __ldg(bias + ob + 2 * p + 1));
        #pragma unroll
        for (int i = 0; i < TC; i++) acc[i][p] = bp;
    }
    __syncthreads();

    // ---- GEMM ----
    #pragma unroll 4
    for (int k = 0; k < K; k++) {
        u64 xd[TC];
        #pragma unroll
        for (int i = 0; i < TC; i++) {
            float xv = Xs[k * PX + cbase + 32 * i];
            xd[i] = pack2(xv, xv);
        }
        const ulonglong2* wq = (const ulonglong2*)(Ws + k * MUL + ob);
        #pragma unroll
        for (int j = 0; j < TOQ; j++) {
            ulonglong2 w2 = wq[j];      // LDS.128 broadcast: 2 natural o-pairs
            #pragma unroll
            for (int i = 0; i < TC; i++) {
                acc[i][2 * j]     = ffma2(xd[i], w2.x, acc[i][2 * j]);
                acc[i][2 * j + 1] = ffma2(xd[i], w2.y, acc[i][2 * j + 1]);
            }
        }
    }
    __syncthreads();

    // ---- stage accumulators: Os[col][o], odd PO -> conflict-free ----
    #pragma unroll
    for (int i = 0; i < TC; i++) {
        int c = cbase + 32 * i;
        #pragma unroll
        for (int p = 0; p < TOH; p++) {
            float lo, hi; unpack2(acc[i][p], lo, hi);
            Os[c * PO + ob + 2 * p]     = lo;
            Os[c * PO + ob + 2 * p + 1] = hi;
        }
    }
    __syncthreads();

    // ---- epilogue: coalesced float4 store ----
    #pragma unroll 1
    for (int i = tid; i < nld; i += NT) {
        int r = i / SEGF4, q = i - r * SEGF4;
        int j = 4 * q;
        float vv[4];
        #pragma unroll
        for (int e = 0; e < 4; e++) {
            int jj = j + e;
            int o  = jj / D;
            int dd = jj - o * D;
            float v = Os[(r * D + dd) * PO + o];
            if (ACT) v = act_fn(v);
            vv[e] = v;
        }
        float4 v; v.x = vv[0]; v.y = vv[1]; v.z = vv[2]; v.w = vv[3];
        *(float4*)(out + (size_t)(r0 + r) * ROWLEN + IN_OFF + 4 * q) = v;
    }
}

extern "C" void kernel_launch(void* const* d_in, const int* in_sizes, int n_in,
                              void* d_out, int out_size) {
    const float* x  = (const float*)d_in[0];
    const float* w0 = (const float*)d_in[1];
    const float* w1 = (const float*)d_in[2];
    const float* w2 = (const float*)d_in[3];
    const float* w3 = (const float*)d_in[4];
    const float* b0 = (const float*)d_in[5];
    const float* b1 = (const float*)d_in[6];
    const float* b2 = (const float*)d_in[7];
    const float* b3 = (const float*)d_in[8];
    float* out = (float*)d_out;
    const int N = in_sizes[0] / ROWLEN;

    //              MUL  D   R NW CW  TO IN_OFF  WOFF   ACT  MINB
    auto k0 = seg_s0<128, 1, 64, 8, 1, 16,    0,     0,  true, 2>;
    auto k1 = seg_s0< 64, 3, 64, 8, 1,  8,  128, 16384, false, 3>;
    auto k2 = seg_s0< 32, 5, 64, 8, 2,  8,  320, 20480, false, 3>;
    auto k3 = seg_s0< 16, 7, 64, 4, 2,  8,  480, 21504, false, 5>;

    // smem bytes: (W + max(Xs, Os)) * 4
    constexpr int S0 = (16384 + ((128 * 65 > 64 * 129) ? 128 * 65 : 64 * 129)) * 4;   // 98816
    constexpr int S1 = (4096  + ((64 * 193 > 192 * 65) ? 64 * 193 : 192 * 65)) * 4;   // 66304
    constexpr int S2 = (1024  + ((32 * 321 > 320 * 33) ? 32 * 321 : 320 * 33)) * 4;   // 46336
    constexpr int S3 = (256   + ((16 * 449 > 448 * 17) ? 16 * 449 : 448 * 17)) * 4;   // 31488

    cudaFuncSetAttribute(k0, cudaFuncAttributeMaxDynamicSharedMemorySize, S0);
    cudaFuncSetAttribute(k1, cudaFuncAttributeMaxDynamicSharedMemorySize, S1);
    cudaFuncSetAttribute(k2, cudaFuncAttributeMaxDynamicSharedMemorySize, S2);
    cudaFuncSetAttribute(k3, cudaFuncAttributeMaxDynamicSharedMemorySize, S3);

    prep_kernel<<<85, 256>>>(w0, w1, w2, w3);

    const int grid = (N + 63) / 64;   // 1563
    k0<<<grid, 256, S0>>>(x, b0, out, N);
    k1<<<grid, 256, S1>>>(x, b1, out, N);
    k2<<<grid, 256, S2>>>(x, b2, out, N);
    k3<<<grid, 128, S3>>>(x, b3, out, N);
}

// round 7
// speedup vs baseline: 1.2382x; 1.0085x over previous
#include <cuda_runtime.h>
#include <cstdint>

typedef unsigned long long u64;
#define DEVINL __device__ __forceinline__

DEVINL u64 pack2(float lo, float hi) {
    u64 d;
    asm("mov.b64 %0, {%1, %2};" : "=l"(d) : "f"(lo), "f"(hi));
    return d;
}
DEVINL void unpack2(u64 v, float& lo, float& hi) {
    asm("mov.b64 {%0, %1}, %2;" : "=f"(lo), "=f"(hi) : "l"(v));
}
DEVINL u64 ffma2(u64 a, u64 b, u64 c) {
    u64 d;
    asm("fma.rn.f32x2 %0, %1, %2, %3;" : "=l"(d) : "l"(a), "l"(b), "l"(c));
    return d;
}

// smooth_leaky_relu(x) = 0.6x + 0.4x*tanh(x/2)   (alpha=0.2)
DEVINL float act_fn(float v) {
    float t;
    asm("tanh.approx.f32 %0, %1;" : "=f"(t) : "f"(0.5f * v));
    return v * (0.6f + 0.4f * t);
}

static constexpr int ROWLEN = 592;

// transposed weights, natural [k][o], packed back-to-back
__device__ float g_wt[21760];

__global__ void prep_kernel(const float* __restrict__ w0, const float* __restrict__ w1,
                            const float* __restrict__ w2, const float* __restrict__ w3) {
    int idx = blockIdx.x * 256 + threadIdx.x;
    if (idx < 16384) {
        int k = idx >> 7, o = idx & 127;
        g_wt[idx] = w0[o * 128 + k];
    } else if (idx < 20480) {
        int t = idx - 16384; int k = t >> 6, o = t & 63;
        g_wt[idx] = w1[o * 64 + k];
    } else if (idx < 21504) {
        int t = idx - 20480; int k = t >> 5, o = t & 31;
        g_wt[idx] = w2[o * 32 + k];
    } else if (idx < 21760) {
        int t = idx - 21504; int k = t >> 4, o = t & 15;
        g_wt[idx] = w3[o * 16 + k];
    }
}

// ===================== transpose-free scheme-0 kernel =====================
// Xs / Os: NATURAL row-major [r][MUL*D], pitch P with P ≡ D (mod 32).
//   bank(x[r][k*D+dd]) ≡ (r*D+dd) + k*D  -> distinct across a warp's columns.
// Ws: natural [k][o]; warp reads its TO outputs 4-at-a-time via LDS.128 broadcast.
// Warps: OW output-groups x CW column-groups; column c = cg*CPW + lane + 32*i.
// acc: TC x TO/2 u64; each u64 = two adjacent outputs (o, o+1) for one column.
template<int MUL, int D, int R, int NW, int CW, int TO,
         int IN_OFF, int WOFF, bool ACT, int MINB>
__global__ __launch_bounds__(NW * 32, MINB)
void seg_s0(const float* __restrict__ x, const float* __restrict__ bias,
            float* __restrict__ out, int N) {
    constexpr int NT     = NW * 32;
    constexpr int K      = MUL;
    constexpr int SEGLEN = MUL * D;
    constexpr int SEGF4  = SEGLEN / 4;
    constexpr int CBLK   = R * D;
    constexpr int OW     = NW / CW;
    constexpr int CPW    = CBLK / CW;
    constexpr int TC     = CPW / 32;
    constexpr int TOH    = TO / 2;
    constexpr int TOQ    = TO / 4;
    // pitch: smallest >= SEGLEN with P ≡ D (mod 32)
    constexpr int P      = SEGLEN + ((32 + D - (SEGLEN % 32)) % 32);
    static_assert(OW * TO == MUL, "");
    static_assert(CPW % 32 == 0, "");
    static_assert(TO % 4 == 0, "");
    static_assert(P % 32 == D % 32, "");

    extern __shared__ float smem[];
    float* Ws = smem;                   // K*MUL
    float* Xs = smem + K * MUL;         // [r][P] natural
    float* Os = Xs;                     // alias after GEMM (same layout)

    const int tid = threadIdx.x, lane = tid & 31, warp = tid >> 5;
    const int r0 = blockIdx.x * R;
    const int nrows = min(R, N - r0);
    const int ob = (warp % OW) * TO;
    const int cbase = (warp / OW) * CPW + lane;

    #pragma unroll 1
    for (int i = tid; i < K * MUL / 4; i += NT)
        ((float4*)Ws)[i] = ((const float4*)(g_wt + WOFF))[i];

    // ---- X load: natural copy, scalar STS (conflict-free; P odd) ----
    const int nld = nrows * SEGF4;
    #pragma unroll 1
    for (int i = tid; i < nld; i += NT) {
        int r = i / SEGF4, q = i - r * SEGF4;
        float4 v = *(const float4*)(x + (size_t)(r0 + r) * ROWLEN + IN_OFF + 4 * q);
        float* dst = Xs + r * P + 4 * q;
        dst[0] = v.x; dst[1] = v.y; dst[2] = v.z; dst[3] = v.w;
    }

    // per-thread column bases: c -> r*P + dd
    int bx[TC];
    #pragma unroll
    for (int i = 0; i < TC; i++) {
        int c = cbase + 32 * i;
        bx[i] = (c / D) * P + (c % D);
    }

    u64 acc[TC][TOH];
    #pragma unroll
    for (int p = 0; p < TOH; p++) {
        u64 bp = pack2(__ldg(bias + ob + 2 * p), __ldg(bias + ob + 2 * p + 1));
        #pragma unroll
        for (int i = 0; i < TC; i++) acc[i][p] = bp;
    }
    __syncthreads();

    // ---- GEMM: x scalar LDS from natural layout, W LDS.128 broadcast ----
    #pragma unroll 4
    for (int k = 0; k < K; k++) {
        u64 xd[TC];
        #pragma unroll
        for (int i = 0; i < TC; i++) {
            float xv = Xs[bx[i] + k * D];
            xd[i] = pack2(xv, xv);
        }
        const ulonglong2* wq = (const ulonglong2*)(Ws + k * MUL + ob);
        #pragma unroll
        for (int j = 0; j < TOQ; j++) {
            ulonglong2 w2 = wq[j];
            #pragma unroll
            for (int i = 0; i < TC; i++) {
                acc[i][2 * j]     = ffma2(xd[i], w2.x, acc[i][2 * j]);
                acc[i][2 * j + 1] = ffma2(xd[i], w2.y, acc[i][2 * j + 1]);
            }
        }
    }
    __syncthreads();

    // ---- stage accumulators into natural Os (banks ≡ c + D*o: conflict-free) ----
    #pragma unroll
    for (int i = 0; i < TC; i++) {
        int c = cbase + 32 * i;
        float* od = Os + (c / D) * P + (c % D);
        #pragma unroll
        for (int p = 0; p < TOH; p++) {
            float lo, hi; unpack2(acc[i][p], lo, hi);
            od[(ob + 2 * p) * D]     = lo;
            od[(ob + 2 * p + 1) * D] = hi;
        }
    }
    __syncthreads();

    // ---- epilogue: natural-order scalar LDS, coalesced float4 STG ----
    #pragma unroll 1
    for (int i = tid; i < nld; i += NT) {
        int r = i / SEGF4, q = i - r * SEGF4;
        const float* src = Os + r * P + 4 * q;
        float4 v;
        if (ACT) {
            v.x = act_fn(src[0]); v.y = act_fn(src[1]);
            v.z = act_fn(src[2]); v.w = act_fn(src[3]);
        } else {
            v.x = src[0]; v.y = src[1]; v.z = src[2]; v.w = src[3];
        }
        *(float4*)(out + (size_t)(r0 + r) * ROWLEN + IN_OFF + 4 * q) = v;
    }
}

// pitch helper (host-side mirror)
constexpr int pitch_of(int seglen, int d) {
    return seglen + ((32 + d - (seglen % 32)) % 32);
}

extern "C" void kernel_launch(void* const* d_in, const int* in_sizes, int n_in,
                              void* d_out, int out_size) {
    const float* x  = (const float*)d_in[0];
    const float* w0 = (const float*)d_in[1];
    const float* w1 = (const float*)d_in[2];
    const float* w2 = (const float*)d_in[3];
    const float* w3 = (const float*)d_in[4];
    const float* b0 = (const float*)d_in[5];
    const float* b1 = (const float*)d_in[6];
    const float* b2 = (const float*)d_in[7];
    const float* b3 = (const float*)d_in[8];
    float* out = (float*)d_out;
    const int N = in_sizes[0] / ROWLEN;

    //              MUL  D   R NW CW  TO IN_OFF  WOFF   ACT  MINB
    auto k0 = seg_s0<128, 1, 64, 8, 1, 16,    0,     0,  true, 2>;
    auto k1 = seg_s0< 64, 3, 64, 8, 2, 16,  128, 16384, false, 3>;
    auto k2 = seg_s0< 32, 5, 64, 8, 2,  8,  320, 20480, false, 3>;
    auto k3 = seg_s0< 16, 7, 32, 4, 1,  4,  480, 21504, false, 6>;

    // smem bytes: (W + R*P) * 4
    constexpr int S0 = (16384 + 64 * pitch_of(128, 1)) * 4;   // (16384+ 8256)*4 = 98560
    constexpr int S1 = (4096  + 64 * pitch_of(192, 3)) * 4;   // (4096 +12480)*4 = 66304
    constexpr int S2 = (1024  + 64 * pitch_of(160, 5)) * 4;   // (1024 +10560)*4 = 46336
    constexpr int S3 = (256   + 32 * pitch_of(112, 7)) * 4;   // (256  + 4320)*4 = 18304

    cudaFuncSetAttribute(k0, cudaFuncAttributeMaxDynamicSharedMemorySize, S0);
    cudaFuncSetAttribute(k1, cudaFuncAttributeMaxDynamicSharedMemorySize, S1);
    cudaFuncSetAttribute(k2, cudaFuncAttributeMaxDynamicSharedMemorySize, S2);
    cudaFuncSetAttribute(k3, cudaFuncAttributeMaxDynamicSharedMemorySize, S3);

    prep_kernel<<<85, 256>>>(w0, w1, w2, w3);

    const int g64 = (N + 63) / 64;   // 1563
    const int g32 = (N + 31) / 32;   // 3125
    k0<<<g64, 256, S0>>>(x, b0, out, N);
    k1<<<g64, 256, S1>>>(x, b1, out, N);
    k2<<<g64, 256, S2>>>(x, b2, out, N);
    k3<<<g32, 128, S3>>>(x, b3, out, N);
}

// round 8
// speedup vs baseline: 1.3729x; 1.1088x over previous
#include <cuda_runtime.h>
#include <cstdint>

typedef unsigned long long u64;
#define DEVINL __device__ __forceinline__

DEVINL u64 pack2(float lo, float hi) {
    u64 d;
    asm("mov.b64 %0, {%1, %2};" : "=l"(d) : "f"(lo), "f"(hi));
    return d;
}
DEVINL void unpack2(u64 v, float& lo, float& hi) {
    asm("mov.b64 {%0, %1}, %2;" : "=f"(lo), "=f"(hi) : "l"(v));
}
DEVINL u64 ffma2(u64 a, u64 b, u64 c) {
    u64 d;
    asm("fma.rn.f32x2 %0, %1, %2, %3;" : "=l"(d) : "l"(a), "l"(b), "l"(c));
    return d;
}

// smooth_leaky_relu(x) = 0.6x + 0.4x*tanh(x/2)   (alpha=0.2)
DEVINL float act_fn(float v) {
    float t;
    asm("tanh.approx.f32 %0, %1;" : "=f"(t) : "f"(0.5f * v));
    return v * (0.6f + 0.4f * t);
}

static constexpr int ROWLEN = 592;

// transposed weights, natural [k][o], packed back-to-back
__device__ float g_wt[21760];

__global__ void prep_kernel(const float* __restrict__ w0, const float* __restrict__ w1,
                            const float* __restrict__ w2, const float* __restrict__ w3) {
    int idx = blockIdx.x * 256 + threadIdx.x;
    if (idx < 16384) {
        int k = idx >> 7, o = idx & 127;
        g_wt[idx] = w0[o * 128 + k];
    } else if (idx < 20480) {
        int t = idx - 16384; int k = t >> 6, o = t & 63;
        g_wt[idx] = w1[o * 64 + k];
    } else if (idx < 21504) {
        int t = idx - 20480; int k = t >> 5, o = t & 31;
        g_wt[idx] = w2[o * 32 + k];
    } else if (idx < 21760) {
        int t = idx - 21504; int k = t >> 4, o = t & 15;
        g_wt[idx] = w3[o * 16 + k];
    }
}

// ===================== transpose-free scheme-0 kernel (unchanged from R7) =====================
// Xs / Os: NATURAL row-major [r][MUL*D], pitch P with P ≡ D (mod 32).
//   bank(x[r][k*D+dd]) ≡ (r*D+dd) + k*D  -> distinct across a warp's columns.
// Ws: natural [k][o]; warp reads its TO outputs 4-at-a-time via LDS.128 broadcast.
// Warps: OW output-groups x CW column-groups; column c = cg*CPW + lane + 32*i.
template<int MUL, int D, int R, int NW, int CW, int TO,
         int IN_OFF, int WOFF, bool ACT, int MINB>
__global__ __launch_bounds__(NW * 32, MINB)
void seg_s0(const float* __restrict__ x, const float* __restrict__ bias,
            float* __restrict__ out, int N) {
    constexpr int NT     = NW * 32;
    constexpr int K      = MUL;
    constexpr int SEGLEN = MUL * D;
    constexpr int SEGF4  = SEGLEN / 4;
    constexpr int CBLK   = R * D;
    constexpr int OW     = NW / CW;
    constexpr int CPW    = CBLK / CW;
    constexpr int TC     = CPW / 32;
    constexpr int TOH    = TO / 2;
    constexpr int TOQ    = TO / 4;
    constexpr int P      = SEGLEN + ((32 + D - (SEGLEN % 32)) % 32);
    static_assert(OW * TO == MUL, "");
    static_assert(CPW % 32 == 0, "");
    static_assert(TO % 4 == 0, "");
    static_assert(P % 32 == D % 32, "");

    extern __shared__ float smem[];
    float* Ws = smem;                   // K*MUL
    float* Xs = smem + K * MUL;         // [r][P] natural
    float* Os = Xs;                     // alias after GEMM (same layout)

    const int tid = threadIdx.x, lane = tid & 31, warp = tid >> 5;
    const int r0 = blockIdx.x * R;
    const int nrows = min(R, N - r0);
    const int ob = (warp % OW) * TO;
    const int cbase = (warp / OW) * CPW + lane;

    #pragma unroll 1
    for (int i = tid; i < K * MUL / 4; i += NT)
        ((float4*)Ws)[i] = ((const float4*)(g_wt + WOFF))[i];

    // ---- X load: natural copy, scalar STS (conflict-free; P odd) ----
    const int nld = nrows * SEGF4;
    #pragma unroll 1
    for (int i = tid; i < nld; i += NT) {
        int r = i / SEGF4, q = i - r * SEGF4;
        float4 v = *(const float4*)(x + (size_t)(r0 + r) * ROWLEN + IN_OFF + 4 * q);
        float* dst = Xs + r * P + 4 * q;
        dst[0] = v.x; dst[1] = v.y; dst[2] = v.z; dst[3] = v.w;
    }

    int bx[TC];
    #pragma unroll
    for (int i = 0; i < TC; i++) {
        int c = cbase + 32 * i;
        bx[i] = (c / D) * P + (c % D);
    }

    u64 acc[TC][TOH];
    #pragma unroll
    for (int p = 0; p < TOH; p++) {
        u64 bp = pack2(__ldg(bias + ob + 2 * p), __ldg(bias + ob + 2 * p + 1));
        #pragma unroll
        for (int i = 0; i < TC; i++) acc[i][p] = bp;
    }
    __syncthreads();

    // ---- GEMM ----
    #pragma unroll 4
    for (int k = 0; k < K; k++) {
        u64 xd[TC];
        #pragma unroll
        for (int i = 0; i < TC; i++) {
            float xv = Xs[bx[i] + k * D];
            xd[i] = pack2(xv, xv);
        }
        const ulonglong2* wq = (const ulonglong2*)(Ws + k * MUL + ob);
        #pragma unroll
        for (int j = 0; j < TOQ; j++) {
            ulonglong2 w2 = wq[j];
            #pragma unroll
            for (int i = 0; i < TC; i++) {
                acc[i][2 * j]     = ffma2(xd[i], w2.x, acc[i][2 * j]);
                acc[i][2 * j + 1] = ffma2(xd[i], w2.y, acc[i][2 * j + 1]);
            }
        }
    }
    __syncthreads();

    // ---- stage accumulators into natural Os (banks ≡ c + D*o: conflict-free) ----
    #pragma unroll
    for (int i = 0; i < TC; i++) {
        int c = cbase + 32 * i;
        float* od = Os + (c / D) * P + (c % D);
        #pragma unroll
        for (int p = 0; p < TOH; p++) {
            float lo, hi; unpack2(acc[i][p], lo, hi);
            od[(ob + 2 * p) * D]     = lo;
            od[(ob + 2 * p + 1) * D] = hi;
        }
    }
    __syncthreads();

    // ---- epilogue: natural-order scalar LDS, coalesced float4 STG ----
    #pragma unroll 1
    for (int i = tid; i < nld; i += NT) {
        int r = i / SEGF4, q = i - r * SEGF4;
        const float* src = Os + r * P + 4 * q;
        float4 v;
        if (ACT) {
            v.x = act_fn(src[0]); v.y = act_fn(src[1]);
            v.z = act_fn(src[2]); v.w = act_fn(src[3]);
        } else {
            v.x = src[0]; v.y = src[1]; v.z = src[2]; v.w = src[3];
        }
        *(float4*)(out + (size_t)(r0 + r) * ROWLEN + IN_OFF + 4 * q) = v;
    }
}

constexpr int pitch_of(int seglen, int d) {
    return seglen + ((32 + d - (seglen % 32)) % 32);
}

// ---- streams/events for fork-join overlap inside the captured graph ----
// Created once on the first (uncaptured, correctness) call; the launched work
// is identical on every call.
static cudaStream_t g_side[3];
static cudaEvent_t  g_ev_root;
static cudaEvent_t  g_ev_done[3];
static bool         g_init_done = false;

extern "C" void kernel_launch(void* const* d_in, const int* in_sizes, int n_in,
                              void* d_out, int out_size) {
    const float* x  = (const float*)d_in[0];
    const float* w0 = (const float*)d_in[1];
    const float* w1 = (const float*)d_in[2];
    const float* w2 = (const float*)d_in[3];
    const float* w3 = (const float*)d_in[4];
    const float* b0 = (const float*)d_in[5];
    const float* b1 = (const float*)d_in[6];
    const float* b2 = (const float*)d_in[7];
    const float* b3 = (const float*)d_in[8];
    float* out = (float*)d_out;
    const int N = in_sizes[0] / ROWLEN;

    if (!g_init_done) {
        for (int i = 0; i < 3; i++)
            cudaStreamCreateWithFlags(&g_side[i], cudaStreamNonBlocking);
        cudaEventCreateWithFlags(&g_ev_root, cudaEventDisableTiming);
        for (int i = 0; i < 3; i++)
            cudaEventCreateWithFlags(&g_ev_done[i], cudaEventDisableTiming);
        g_init_done = true;
    }

    //              MUL  D   R NW CW  TO IN_OFF  WOFF   ACT  MINB
    auto k0 = seg_s0<128, 1, 64, 8, 1, 16,    0,     0,  true, 2>;
    auto k1 = seg_s0< 64, 3, 64, 8, 2, 16,  128, 16384, false, 3>;
    auto k2 = seg_s0< 32, 5, 64, 8, 2,  8,  320, 20480, false, 3>;
    auto k3 = seg_s0< 16, 7, 32, 4, 1,  4,  480, 21504, false, 6>;

    constexpr int S0 = (16384 + 64 * pitch_of(128, 1)) * 4;   // 98560
    constexpr int S1 = (4096  + 64 * pitch_of(192, 3)) * 4;   // 66304
    constexpr int S2 = (1024  + 64 * pitch_of(160, 5)) * 4;   // 46336
    constexpr int S3 = (256   + 32 * pitch_of(112, 7)) * 4;   // 18304

    cudaFuncSetAttribute(k0, cudaFuncAttributeMaxDynamicSharedMemorySize, S0);
    cudaFuncSetAttribute(k1, cudaFuncAttributeMaxDynamicSharedMemorySize, S1);
    cudaFuncSetAttribute(k2, cudaFuncAttributeMaxDynamicSharedMemorySize, S2);
    cudaFuncSetAttribute(k3, cudaFuncAttributeMaxDynamicSharedMemorySize, S3);

    // ---- fork: prep on main stream, segs 1..3 on side streams ----
    prep_kernel<<<85, 256>>>(w0, w1, w2, w3);
    cudaEventRecord(g_ev_root, 0);
    for (int i = 0; i < 3; i++)
        cudaStreamWaitEvent(g_side[i], g_ev_root, 0);

    const int g64 = (N + 63) / 64;   // 1563
    const int g32 = (N + 31) / 32;   // 3125

    k0<<<g64, 256, S0>>>(x, b0, out, N);                 // main stream
    k1<<<g64, 256, S1, g_side[0]>>>(x, b1, out, N);
    k2<<<g64, 256, S2, g_side[1]>>>(x, b2, out, N);
    k3<<<g32, 128, S3, g_side[2]>>>(x, b3, out, N);

    // ---- join back onto the main (capture) stream ----
    for (int i = 0; i < 3; i++) {
        cudaEventRecord(g_ev_done[i], g_side[i]);
        cudaStreamWaitEvent(0, g_ev_done[i], 0);
    }
}